// round 1
// baseline (speedup 1.0000x reference)
#include <cuda_runtime.h>

#define N_PIX 4096
#define M_PIX 1024

// Scratch (device globals — no allocation allowed)
__device__ __align__(16) float g_q[16 * 16 * N_PIX];   // [b][16][n]
__device__ __align__(16) float g_k[16 * 16 * M_PIX];   // [b][16][m]
__device__ __align__(16) float g_v[16 * 64 * M_PIX];   // [b][64][m]

// ---------------------------------------------------------------------------
// Kernel 1: q/k/v 1x1-conv projections + 2x2 maxpool for k,v.
// Block = 128 threads = 128 consecutive pixels = 2 full image rows (h0 even),
// so every 2x2 pool window is fully inside the block.
// ---------------------------------------------------------------------------
__global__ __launch_bounds__(128) void proj_pool_kernel(
    const float* __restrict__ x,
    const float* __restrict__ wq,
    const float* __restrict__ wk,
    const float* __restrict__ wv)
{
    extern __shared__ float sm[];
    float* sW = sm;                 // 96*128 floats (wq rows 0-15, wk 16-31, wv 32-95)
    float* kb = sm + 96 * 128;      // 128 * 17
    float* vb = kb + 128 * 17;      // 128 * 65

    const int t = threadIdx.x;
    for (int i = t; i < 2048; i += 128) sW[i] = wq[i];
    for (int i = t; i < 2048; i += 128) sW[2048 + i] = wk[i];
    for (int i = t; i < 8192; i += 128) sW[4096 + i] = wv[i];
    __syncthreads();

    const int b = blockIdx.y;
    const int n = blockIdx.x * 128 + t;
    const float* xb = x + (size_t)b * 128 * N_PIX;

    float qa[16], ka[16], va[64];
#pragma unroll
    for (int o = 0; o < 16; o++) { qa[o] = 0.f; ka[o] = 0.f; }
#pragma unroll
    for (int o = 0; o < 64; o++) va[o] = 0.f;

#pragma unroll 2
    for (int c = 0; c < 128; c++) {
        float xv = xb[c * N_PIX + n];
#pragma unroll
        for (int o = 0; o < 16; o++) qa[o] = fmaf(sW[o * 128 + c], xv, qa[o]);
#pragma unroll
        for (int o = 0; o < 16; o++) ka[o] = fmaf(sW[2048 + o * 128 + c], xv, ka[o]);
#pragma unroll
        for (int o = 0; o < 64; o++) va[o] = fmaf(sW[4096 + o * 128 + c], xv, va[o]);
    }

#pragma unroll
    for (int o = 0; o < 16; o++) g_q[(b * 16 + o) * N_PIX + n] = qa[o];
#pragma unroll
    for (int o = 0; o < 16; o++) kb[t * 17 + o] = ka[o];
#pragma unroll
    for (int o = 0; o < 64; o++) vb[t * 65 + o] = va[o];
    __syncthreads();

    // Pool: block covers image rows h0, h0+1 (h0 = 2*blockIdx.x) -> pooled row hp = blockIdx.x.
    // 32 pooled columns x 80 channels = 2560 tasks.
    const int mbase = blockIdx.x * 32;
    for (int idx = t; idx < 2560; idx += 128) {
        int ch = idx >> 5, wp = idx & 31;
        int t00 = wp * 2, t01 = t00 + 1, t10 = t00 + 64, t11 = t00 + 65;
        if (ch < 16) {
            float r = fmaxf(fmaxf(kb[t00 * 17 + ch], kb[t01 * 17 + ch]),
                            fmaxf(kb[t10 * 17 + ch], kb[t11 * 17 + ch]));
            g_k[((b * 16 + ch) << 10) + mbase + wp] = r;
        } else {
            int c2 = ch - 16;
            float r = fmaxf(fmaxf(vb[t00 * 65 + c2], vb[t01 * 65 + c2]),
                            fmaxf(vb[t10 * 65 + c2], vb[t11 * 65 + c2]));
            g_v[((b * 64 + c2) << 10) + mbase + wp] = r;
        }
    }
}

// ---------------------------------------------------------------------------
// Kernel 2: fused attention per (batch, 32-query tile).
// SMEM: P[32][1028] scores (128KB), KV buffer 64KB (K, then V chunks, then
// wo^T), Q tile, O tile, inv-rowsum. ~203 KB total -> 1 CTA/SM.
// ---------------------------------------------------------------------------
__global__ __launch_bounds__(256) void attn_kernel(
    const float* __restrict__ x,
    const float* __restrict__ wo,
    const float* __restrict__ gamma,
    float* __restrict__ out)
{
    extern __shared__ float sm[];
    float* sP   = sm;                    // 32 * 1028
    float* sKV  = sP + 32 * 1028;        // 16384 floats (64KB), multi-purpose
    float* sQ   = sKV + 16384;           // 16 * 32
    float* sO   = sQ + 512;              // 64 * 33
    float* sInv = sO + 64 * 33;          // 32

    const int t  = threadIdx.x;
    const int b  = blockIdx.y;
    const int n0 = blockIdx.x * 32;

    // Load K [16][1024] into sKV (float4, coalesced)
    {
        const float4* gk4 = (const float4*)(g_k + b * 16 * M_PIX);
        float4* sk4 = (float4*)sKV;
#pragma unroll
        for (int i = 0; i < 16; i++) sk4[t + i * 256] = gk4[t + i * 256];
    }
    // Load Q tile [16][32]
    for (int i = t; i < 512; i += 256) {
        int d = i >> 5, j = i & 31;
        sQ[i] = g_q[(b * 16 + d) * N_PIX + n0 + j];
    }
    __syncthreads();

    // ---- Phase 1: scores S[n][m] = sum_d q[d,n] * k[d,m] ----
    {
        const int nr = t >> 3, l8 = t & 7;
        float qr[16];
#pragma unroll
        for (int d = 0; d < 16; d++) qr[d] = sQ[d * 32 + nr];
        for (int j = 0; j < 32; j++) {
            int m = l8 * 4 + j * 32;
            float4 acc = make_float4(0.f, 0.f, 0.f, 0.f);
#pragma unroll
            for (int d = 0; d < 16; d++) {
                float4 kv = *(const float4*)&sKV[d * 1024 + m];
                acc.x = fmaf(qr[d], kv.x, acc.x);
                acc.y = fmaf(qr[d], kv.y, acc.y);
                acc.z = fmaf(qr[d], kv.z, acc.z);
                acc.w = fmaf(qr[d], kv.w, acc.w);
            }
            *(float4*)&sP[nr * 1028 + m] = acc;
        }
    }
    __syncthreads();

    // ---- Softmax rows: exp in place, 1/sum deferred to epilogue ----
    {
        const int warp = t >> 5, lane = t & 31;
#pragma unroll
        for (int rr = 0; rr < 4; rr++) {
            int r = warp * 4 + rr;
            float* row = sP + r * 1028;
            float mx = -1e30f;
            for (int i = lane; i < 1024; i += 32) mx = fmaxf(mx, row[i]);
#pragma unroll
            for (int s = 16; s > 0; s >>= 1) mx = fmaxf(mx, __shfl_xor_sync(0xffffffffu, mx, s));
            float sum = 0.f;
            for (int i = lane; i < 1024; i += 32) {
                float e = __expf(row[i] - mx);
                row[i] = e;
                sum += e;
            }
#pragma unroll
            for (int s = 16; s > 0; s >>= 1) sum += __shfl_xor_sync(0xffffffffu, sum, s);
            if (lane == 0) sInv[r] = 1.f / sum;
        }
    }
    __syncthreads();

    // ---- Phase 2: o[c][n] = sum_m v[c][m] * P[n][m] ----
    // thread tile: 4 c x 2 n ; V streamed in [64][64] chunks into sKV.
    const int cg = t >> 4;          // 0..15 -> c0 = 4*cg
    const int ng = t & 15;          // n pair = {2ng, 2ng+1}
    float acc[4][2];
#pragma unroll
    for (int i = 0; i < 4; i++) { acc[i][0] = 0.f; acc[i][1] = 0.f; }

    const float* gv = g_v + b * 64 * M_PIX;
    for (int chunk = 0; chunk < 16; ++chunk) {
        const int m0 = chunk * 64;
        __syncthreads();  // previous chunk fully consumed
        for (int i = t; i < 4096; i += 256) {
            int c = i >> 6, mm = i & 63;
            sKV[c * 68 + mm] = gv[c * 1024 + m0 + mm];
        }
        __syncthreads();
        const float* prow0 = sP + (ng * 2) * 1028 + m0;
        const float* prow1 = prow0 + 1028;
#pragma unroll 4
        for (int mm = 0; mm < 64; mm += 4) {
            float4 p0 = *(const float4*)(prow0 + mm);
            float4 p1 = *(const float4*)(prow1 + mm);
#pragma unroll
            for (int i = 0; i < 4; i++) {
                float4 v4 = *(const float4*)&sKV[(cg * 4 + i) * 68 + mm];
                acc[i][0] = fmaf(v4.x, p0.x, acc[i][0]);
                acc[i][0] = fmaf(v4.y, p0.y, acc[i][0]);
                acc[i][0] = fmaf(v4.z, p0.z, acc[i][0]);
                acc[i][0] = fmaf(v4.w, p0.w, acc[i][0]);
                acc[i][1] = fmaf(v4.x, p1.x, acc[i][1]);
                acc[i][1] = fmaf(v4.y, p1.y, acc[i][1]);
                acc[i][1] = fmaf(v4.z, p1.z, acc[i][1]);
                acc[i][1] = fmaf(v4.w, p1.w, acc[i][1]);
            }
        }
    }
    __syncthreads();

    // stash o tile, load wo^T into sKV
#pragma unroll
    for (int i = 0; i < 4; i++) {
#pragma unroll
        for (int j = 0; j < 2; j++)
            sO[(cg * 4 + i) * 33 + ng * 2 + j] = acc[i][j];
    }
    for (int i = t; i < 8192; i += 256) {
        int c = i >> 7, o = i & 127;
        sKV[c * 128 + o] = wo[o * 64 + c];   // wo is [128][64]
    }
    __syncthreads();

    // ---- Phase 3: out[o][n] = gamma * inv[n] * sum_c wo[o][c]*o_raw[c][n] + x ----
    {
        const int nn = t & 31;
        const int og = t >> 5;               // o base = 16*og
        float oa[16];
#pragma unroll
        for (int kk = 0; kk < 16; kk++) oa[kk] = 0.f;
        for (int c = 0; c < 64; c++) {
            float ov = sO[c * 33 + nn];
            const float4* w4 = (const float4*)&sKV[c * 128 + og * 16];
#pragma unroll
            for (int q4 = 0; q4 < 4; q4++) {
                float4 w = w4[q4];
                oa[q4 * 4 + 0] = fmaf(w.x, ov, oa[q4 * 4 + 0]);
                oa[q4 * 4 + 1] = fmaf(w.y, ov, oa[q4 * 4 + 1]);
                oa[q4 * 4 + 2] = fmaf(w.z, ov, oa[q4 * 4 + 2]);
                oa[q4 * 4 + 3] = fmaf(w.w, ov, oa[q4 * 4 + 3]);
            }
        }
        const float gsc = gamma[0] * sInv[nn];
        const size_t base = (size_t)(b * 128) * N_PIX + n0 + nn;
#pragma unroll
        for (int kk = 0; kk < 16; kk++) {
            int o = og * 16 + kk;
            size_t gi = base + (size_t)o * N_PIX;
            out[gi] = fmaf(gsc, oa[kk], x[gi]);
        }
    }
}

// ---------------------------------------------------------------------------
extern "C" void kernel_launch(void* const* d_in, const int* in_sizes, int n_in,
                              void* d_out, int out_size)
{
    const float* x     = (const float*)d_in[0];
    const float* wq    = (const float*)d_in[1];
    const float* wk    = (const float*)d_in[2];
    const float* wv    = (const float*)d_in[3];
    const float* wo    = (const float*)d_in[4];
    const float* gamma = (const float*)d_in[5];
    float* out = (float*)d_out;

    const int smem1 = (96 * 128 + 128 * 17 + 128 * 65) * 4;                 // 91136
    const int smem2 = (32 * 1028 + 16384 + 512 + 64 * 33 + 32) * 4;        // 207744

    cudaFuncSetAttribute(proj_pool_kernel, cudaFuncAttributeMaxDynamicSharedMemorySize, smem1);
    cudaFuncSetAttribute(attn_kernel,      cudaFuncAttributeMaxDynamicSharedMemorySize, smem2);

    proj_pool_kernel<<<dim3(32, 16), 128, smem1>>>(x, wq, wk, wv);
    attn_kernel<<<dim3(128, 16), 256, smem2>>>(x, wo, gamma, out);
}

// round 2
// speedup vs baseline: 1.1948x; 1.1948x over previous
#include <cuda_runtime.h>

#define N_PIX 4096
#define M_PIX 1024
#define PSTR 1028

// Scratch (device globals — no allocation allowed)
__device__ __align__(16) float g_q[16 * 16 * N_PIX];   // [b][16][n]
__device__ __align__(16) float g_k[16 * 16 * M_PIX];   // [b][16][m]
__device__ __align__(16) float g_v[16 * 64 * M_PIX];   // [b][64][m]

// ---------------------------------------------------------------------------
// Kernel 1: q/k/v 1x1-conv projections + 2x2 maxpool for k,v. (unchanged)
// ---------------------------------------------------------------------------
__global__ __launch_bounds__(128) void proj_pool_kernel(
    const float* __restrict__ x,
    const float* __restrict__ wq,
    const float* __restrict__ wk,
    const float* __restrict__ wv)
{
    extern __shared__ float sm[];
    float* sW = sm;                 // 96*128
    float* kb = sm + 96 * 128;      // 128 * 17
    float* vb = kb + 128 * 17;      // 128 * 65

    const int t = threadIdx.x;
    for (int i = t; i < 2048; i += 128) sW[i] = wq[i];
    for (int i = t; i < 2048; i += 128) sW[2048 + i] = wk[i];
    for (int i = t; i < 8192; i += 128) sW[4096 + i] = wv[i];
    __syncthreads();

    const int b = blockIdx.y;
    const int n = blockIdx.x * 128 + t;
    const float* xb = x + (size_t)b * 128 * N_PIX;

    float qa[16], ka[16], va[64];
#pragma unroll
    for (int o = 0; o < 16; o++) { qa[o] = 0.f; ka[o] = 0.f; }
#pragma unroll
    for (int o = 0; o < 64; o++) va[o] = 0.f;

#pragma unroll 2
    for (int c = 0; c < 128; c++) {
        float xv = xb[c * N_PIX + n];
#pragma unroll
        for (int o = 0; o < 16; o++) qa[o] = fmaf(sW[o * 128 + c], xv, qa[o]);
#pragma unroll
        for (int o = 0; o < 16; o++) ka[o] = fmaf(sW[2048 + o * 128 + c], xv, ka[o]);
#pragma unroll
        for (int o = 0; o < 64; o++) va[o] = fmaf(sW[4096 + o * 128 + c], xv, va[o]);
    }

#pragma unroll
    for (int o = 0; o < 16; o++) g_q[(b * 16 + o) * N_PIX + n] = qa[o];
#pragma unroll
    for (int o = 0; o < 16; o++) kb[t * 17 + o] = ka[o];
#pragma unroll
    for (int o = 0; o < 64; o++) vb[t * 65 + o] = va[o];
    __syncthreads();

    const int mbase = blockIdx.x * 32;
    for (int idx = t; idx < 2560; idx += 128) {
        int ch = idx >> 5, wp = idx & 31;
        int t00 = wp * 2, t01 = t00 + 1, t10 = t00 + 64, t11 = t00 + 65;
        if (ch < 16) {
            float r = fmaxf(fmaxf(kb[t00 * 17 + ch], kb[t01 * 17 + ch]),
                            fmaxf(kb[t10 * 17 + ch], kb[t11 * 17 + ch]));
            g_k[((b * 16 + ch) << 10) + mbase + wp] = r;
        } else {
            int c2 = ch - 16;
            float r = fmaxf(fmaxf(vb[t00 * 65 + c2], vb[t01 * 65 + c2]),
                            fmaxf(vb[t10 * 65 + c2], vb[t11 * 65 + c2]));
            g_v[((b * 64 + c2) << 10) + mbase + wp] = r;
        }
    }
}

// ---------------------------------------------------------------------------
// Kernel 2: fused attention per (batch, 32-query tile). 512 threads.
// SMEM: sP[32][1028] (128.5KB), sV 16640 fl (K / V-chunks / wo^T),
//       sQ 512, sO 64x33, sInv 32. Total ~204KB -> 1 CTA/SM, 16 warps.
// ---------------------------------------------------------------------------
__global__ __launch_bounds__(512) void attn_kernel(
    const float* __restrict__ x,
    const float* __restrict__ wo,
    const float* __restrict__ gamma,
    float* __restrict__ out)
{
    extern __shared__ float sm[];
    float* sP   = sm;                    // 32 * 1028 = 32896
    float* sV   = sP + 32 * PSTR;        // 16640 floats, multi-purpose
    float* sQ   = sV + 16640;            // 512
    float* sO   = sQ + 512;              // 64 * 33 = 2112
    float* sInv = sO + 2112;             // 32

    const int t    = threadIdx.x;
    const int w    = t >> 5;
    const int lane = t & 31;
    const int b    = blockIdx.y;
    const int n0   = blockIdx.x * 32;

    // ---- Stage K [16][1024] into sV, Q tile [16][32] into sQ ----
    {
        const float4* gk4 = (const float4*)(g_k + b * 16 * M_PIX);
        float4* s4 = (float4*)sV;
#pragma unroll
        for (int i = 0; i < 8; i++) s4[t + i * 512] = gk4[t + i * 512];
        sQ[t] = g_q[(b * 16 + (t >> 5)) * N_PIX + n0 + (t & 31)];
    }
    __syncthreads();

    // ---- Phase 1: S[n][m] = sum_d q[d,n]*k[d,m];  thread: 1n x 64m ----
    {
        const int n = t >> 4, ml = t & 15;
        float qr[16];
#pragma unroll
        for (int d = 0; d < 16; d++) qr[d] = sQ[d * 32 + n];
#pragma unroll 2
        for (int it = 0; it < 16; it++) {
            int m = it * 64 + ml * 4;
            float4 acc = make_float4(0.f, 0.f, 0.f, 0.f);
#pragma unroll
            for (int d = 0; d < 16; d++) {
                float4 kv = *(const float4*)&sV[d * 1024 + m];
                acc.x = fmaf(qr[d], kv.x, acc.x);
                acc.y = fmaf(qr[d], kv.y, acc.y);
                acc.z = fmaf(qr[d], kv.z, acc.z);
                acc.w = fmaf(qr[d], kv.w, acc.w);
            }
            *(float4*)&sP[n * PSTR + m] = acc;
        }
    }
    __syncthreads();

    // ---- Softmax: warp handles rows 2w, 2w+1; exp in place, 1/sum deferred ----
    {
#pragma unroll
        for (int rr = 0; rr < 2; rr++) {
            int r = w * 2 + rr;
            float* row = sP + r * PSTR;
            float mx = -1e30f;
#pragma unroll
            for (int i = 0; i < 8; i++) {
                float4 v = *(const float4*)&row[(lane + i * 32) * 4];
                mx = fmaxf(mx, fmaxf(fmaxf(v.x, v.y), fmaxf(v.z, v.w)));
            }
#pragma unroll
            for (int s = 16; s > 0; s >>= 1) mx = fmaxf(mx, __shfl_xor_sync(0xffffffffu, mx, s));
            float sum = 0.f;
#pragma unroll
            for (int i = 0; i < 8; i++) {
                float4* p = (float4*)&row[(lane + i * 32) * 4];
                float4 v = *p;
                v.x = __expf(v.x - mx); v.y = __expf(v.y - mx);
                v.z = __expf(v.z - mx); v.w = __expf(v.w - mx);
                *p = v;
                sum += v.x + v.y + v.z + v.w;
            }
#pragma unroll
            for (int s = 16; s > 0; s >>= 1) sum += __shfl_xor_sync(0xffffffffu, sum, s);
            if (lane == 0) sInv[r] = 1.f / sum;
        }
    }
    __syncthreads();

    // ---- Phase 2: o[c][n] = sum_m v[c][m]*P[n][m] ----
    // warp: c-group (w>>2)*16, m-quarter (w&3). thread: 8c x 2n over m/4.
    const int mq  = w & 3;
    const int np  = lane & 15;
    const int c0  = (w >> 2) * 16 + (lane >> 4) * 8;
    float acc[8][2];
#pragma unroll
    for (int i = 0; i < 8; i++) { acc[i][0] = 0.f; acc[i][1] = 0.f; }

    const float4* gv4 = (const float4*)(g_v + b * 64 * M_PIX);
    for (int chk = 0; chk < 4; chk++) {
        __syncthreads();   // previous chunk (or K) fully consumed
        // stage V[64][4 quarters][64m] for this chk: 4096 float4, 8 per thread
#pragma unroll
        for (int j = 0; j < 8; j++) {
            int idx = t * 8 + j;          // 0..4095
            int off = idx & 15;           // f4 within 64m
            int p   = idx >> 4;           // 0..255
            int c   = p >> 2, qd = p & 3;
            ((float4*)sV)[c * 65 + qd * 16 + off] =
                gv4[c * 256 + qd * 64 + chk * 16 + off];
        }
        __syncthreads();

        const float* pr0 = sP + np * PSTR + mq * 256 + chk * 64;
        const float* pr1 = pr0 + 16 * PSTR;
        const float* vb  = sV + mq * 64;
#pragma unroll 4
        for (int mm = 0; mm < 64; mm += 4) {
            float4 p0 = *(const float4*)(pr0 + mm);
            float4 p1 = *(const float4*)(pr1 + mm);
#pragma unroll
            for (int i = 0; i < 8; i++) {
                float4 v4 = *(const float4*)&vb[(c0 + i) * 260 + mm];
                acc[i][0] = fmaf(v4.x, p0.x, acc[i][0]);
                acc[i][0] = fmaf(v4.y, p0.y, acc[i][0]);
                acc[i][0] = fmaf(v4.z, p0.z, acc[i][0]);
                acc[i][0] = fmaf(v4.w, p0.w, acc[i][0]);
                acc[i][1] = fmaf(v4.x, p1.x, acc[i][1]);
                acc[i][1] = fmaf(v4.y, p1.y, acc[i][1]);
                acc[i][1] = fmaf(v4.z, p1.z, acc[i][1]);
                acc[i][1] = fmaf(v4.w, p1.w, acc[i][1]);
            }
        }
    }
    __syncthreads();   // P + V now dead

    // ---- Reduce 4 m-quarters. Partials from mq=1..3 go into sP (dead). ----
    float* sRed = sP;  // 3 buffers of 64*33
    if (mq > 0) {
        float* rb = sRed + (mq - 1) * 2112;
#pragma unroll
        for (int i = 0; i < 8; i++) {
            rb[(c0 + i) * 33 + np]      = acc[i][0];
            rb[(c0 + i) * 33 + np + 16] = acc[i][1];
        }
    }
    // stage wo^T into sV (dead): sWo[c][o], 64*128
    for (int i = t; i < 8192; i += 512) {
        int c = i >> 7, o = i & 127;
        sV[c * 128 + o] = wo[o * 64 + c];
    }
    __syncthreads();
    if (mq == 0) {
#pragma unroll
        for (int i = 0; i < 8; i++) {
            int c = c0 + i;
            sO[c * 33 + np] = acc[i][0] + sRed[c * 33 + np]
                            + sRed[2112 + c * 33 + np] + sRed[4224 + c * 33 + np];
            sO[c * 33 + np + 16] = acc[i][1] + sRed[c * 33 + np + 16]
                            + sRed[2112 + c * 33 + np + 16] + sRed[4224 + c * 33 + np + 16];
        }
    }
    __syncthreads();

    // ---- Phase 3: out[o][n] = gamma*inv[n]*sum_c wo[o][c]*o_raw[c][n] + x ----
    {
        const int nn = lane;
        const int og = w;               // o = og*8 .. og*8+7
        float oa[8];
#pragma unroll
        for (int k = 0; k < 8; k++) oa[k] = 0.f;
        for (int c = 0; c < 64; c++) {
            float ov = sO[c * 33 + nn];
            const float4* w4 = (const float4*)&sV[c * 128 + og * 8];
            float4 wA = w4[0], wB = w4[1];
            oa[0] = fmaf(wA.x, ov, oa[0]);
            oa[1] = fmaf(wA.y, ov, oa[1]);
            oa[2] = fmaf(wA.z, ov, oa[2]);
            oa[3] = fmaf(wA.w, ov, oa[3]);
            oa[4] = fmaf(wB.x, ov, oa[4]);
            oa[5] = fmaf(wB.y, ov, oa[5]);
            oa[6] = fmaf(wB.z, ov, oa[6]);
            oa[7] = fmaf(wB.w, ov, oa[7]);
        }
        const float gsc = gamma[0] * sInv[nn];
        const size_t base = (size_t)(b * 128) * N_PIX + n0 + nn;
#pragma unroll
        for (int k = 0; k < 8; k++) {
            size_t gi = base + (size_t)(og * 8 + k) * N_PIX;
            out[gi] = fmaf(gsc, oa[k], x[gi]);
        }
    }
}

// ---------------------------------------------------------------------------
extern "C" void kernel_launch(void* const* d_in, const int* in_sizes, int n_in,
                              void* d_out, int out_size)
{
    const float* x     = (const float*)d_in[0];
    const float* wq    = (const float*)d_in[1];
    const float* wk    = (const float*)d_in[2];
    const float* wv    = (const float*)d_in[3];
    const float* wo    = (const float*)d_in[4];
    const float* gamma = (const float*)d_in[5];
    float* out = (float*)d_out;

    const int smem1 = (96 * 128 + 128 * 17 + 128 * 65) * 4;                  // 91136
    const int smem2 = (32 * PSTR + 16640 + 512 + 64 * 33 + 32) * 4;          // 208768

    cudaFuncSetAttribute(proj_pool_kernel, cudaFuncAttributeMaxDynamicSharedMemorySize, smem1);
    cudaFuncSetAttribute(attn_kernel,      cudaFuncAttributeMaxDynamicSharedMemorySize, smem2);

    proj_pool_kernel<<<dim3(32, 16), 128, smem1>>>(x, wq, wk, wv);
    attn_kernel<<<dim3(128, 16), 512, smem2>>>(x, wo, gamma, out);
}